// round 4
// baseline (speedup 1.0000x reference)
#include <cuda_runtime.h>
#include <cuda_bf16.h>
#include <cstdint>

#define N_NODES   100000
#define N_EDGES   1600000
#define DFEAT     32
#define SCAN_B    256
#define NBLK      ((N_NODES + SCAN_B - 1) / SCAN_B)   // 391

// Scratch (device globals; no allocation). Rebuilt on every launch/replay.
__device__ int g_count[N_NODES];
__device__ int g_cursor[N_NODES];
__device__ int g_row_start[N_NODES + 1];
__device__ int g_bsum[NBLK];
__device__ int g_boff[NBLK];
__device__ int g_perm[N_EDGES];

// ---------------------------------------------------------------------------
// 1) zero the histogram
// ---------------------------------------------------------------------------
__global__ void k_zero_count() {
    int i = blockIdx.x * blockDim.x + threadIdx.x;
    if (i < N_NODES) g_count[i] = 0;
}

// ---------------------------------------------------------------------------
// 2) histogram of dst (int atomics, 100K spread addresses)
// ---------------------------------------------------------------------------
__global__ void k_hist(const int* __restrict__ dst) {
    int e = blockIdx.x * blockDim.x + threadIdx.x;
    if (e < N_EDGES) atomicAdd(&g_count[dst[e]], 1);
}

// ---------------------------------------------------------------------------
// 3a) per-block sums of count
// ---------------------------------------------------------------------------
__global__ void k_scan1() {
    __shared__ int sh[SCAN_B];
    int t = threadIdx.x;
    int i = blockIdx.x * SCAN_B + t;
    sh[t] = (i < N_NODES) ? g_count[i] : 0;
    __syncthreads();
    for (int off = SCAN_B / 2; off > 0; off >>= 1) {
        if (t < off) sh[t] += sh[t + off];
        __syncthreads();
    }
    if (t == 0) g_bsum[blockIdx.x] = sh[0];
}

// ---------------------------------------------------------------------------
// 3b) serial exclusive scan of 391 block sums (single thread; trivial)
// ---------------------------------------------------------------------------
__global__ void k_scan2() {
    int acc = 0;
    for (int b = 0; b < NBLK; b++) {
        g_boff[b] = acc;
        acc += g_bsum[b];
    }
    g_row_start[N_NODES] = acc;   // == N_EDGES
}

// ---------------------------------------------------------------------------
// 3c) in-block exclusive scan + offset -> row_start, cursor
// ---------------------------------------------------------------------------
__global__ void k_scan3() {
    __shared__ int sh[SCAN_B];
    int t = threadIdx.x;
    int i = blockIdx.x * SCAN_B + t;
    int v = (i < N_NODES) ? g_count[i] : 0;
    sh[t] = v;
    __syncthreads();
    for (int off = 1; off < SCAN_B; off <<= 1) {
        int x = (t >= off) ? sh[t - off] : 0;
        __syncthreads();
        sh[t] += x;
        __syncthreads();
    }
    if (i < N_NODES) {
        int excl = g_boff[blockIdx.x] + sh[t] - v;
        g_row_start[i] = excl;
        g_cursor[i]    = excl;
    }
}

// ---------------------------------------------------------------------------
// 4) scatter edge ids into dst-grouped perm
// ---------------------------------------------------------------------------
__global__ void k_fill_perm(const int* __restrict__ dst) {
    int e = blockIdx.x * blockDim.x + threadIdx.x;
    if (e < N_EDGES) {
        int p = atomicAdd(&g_cursor[dst[e]], 1);
        g_perm[p] = e;
    }
}

// ---------------------------------------------------------------------------
// 5) fused aggregation + linear. One warp per node; lane = feature.
//    acc[lane] = sum over incoming edges of relu(x[src] + e) -- in registers.
//    Then h = (1+eps)*x[n] + acc; out = h @ W^T + b via shfl-GEMV.
// ---------------------------------------------------------------------------
__global__ void k_agg_linear(const float* __restrict__ node_inputs,
                             const float* __restrict__ edge_inputs,
                             const int*   __restrict__ src,
                             const float* __restrict__ W,
                             const float* __restrict__ b,
                             const float* __restrict__ eps,
                             float*       __restrict__ out) {
    int gtid = blockIdx.x * blockDim.x + threadIdx.x;
    int n    = gtid >> 5;        // node id (warp per node)
    int lane = threadIdx.x & 31;
    if (n >= N_NODES) return;

    // W row for this output feature, in registers (L1-hit after warm).
    float w[32];
#pragma unroll
    for (int k = 0; k < 32; k++) w[k] = __ldg(&W[lane * 32 + k]);
    float bias = __ldg(&b[lane]);
    float ep1  = 1.0f + __ldg(&eps[0]);

    int begin = g_row_start[n];
    int end   = g_row_start[n + 1];

    // 2-way unrolled edge loop for MLP on the dependent perm->src->row chain.
    float acc0 = 0.f, acc1 = 0.f;
    int i = begin;
    for (; i + 1 < end; i += 2) {
        int e0 = __ldg(&g_perm[i]);
        int e1 = __ldg(&g_perm[i + 1]);
        int s0 = __ldg(&src[e0]);
        int s1 = __ldg(&src[e1]);
        float m0 = node_inputs[(size_t)s0 * 32 + lane]
                 + edge_inputs[(size_t)e0 * 32 + lane];
        float m1 = node_inputs[(size_t)s1 * 32 + lane]
                 + edge_inputs[(size_t)e1 * 32 + lane];
        acc0 += fmaxf(m0, 0.f);
        acc1 += fmaxf(m1, 0.f);
    }
    if (i < end) {
        int e0 = __ldg(&g_perm[i]);
        int s0 = __ldg(&src[e0]);
        float m0 = node_inputs[(size_t)s0 * 32 + lane]
                 + edge_inputs[(size_t)e0 * 32 + lane];
        acc0 += fmaxf(m0, 0.f);
    }

    float h = ep1 * node_inputs[(size_t)n * 32 + lane] + (acc0 + acc1);

    // GEMV: out[n][lane] = bias + sum_k h_k * W[lane][k], h_k via shfl.
    float a0 = bias, a1 = 0.f, a2 = 0.f, a3 = 0.f;
#pragma unroll
    for (int k = 0; k < 32; k += 4) {
        a0 = fmaf(__shfl_sync(0xffffffffu, h, k + 0), w[k + 0], a0);
        a1 = fmaf(__shfl_sync(0xffffffffu, h, k + 1), w[k + 1], a1);
        a2 = fmaf(__shfl_sync(0xffffffffu, h, k + 2), w[k + 2], a2);
        a3 = fmaf(__shfl_sync(0xffffffffu, h, k + 3), w[k + 3], a3);
    }
    out[(size_t)n * 32 + lane] = (a0 + a1) + (a2 + a3);
}

// ---------------------------------------------------------------------------
// Launch sequence (all on capture stream, serialized).
// Inputs: node_inputs, edge_inputs, src, dst, W, b, eps.
// ---------------------------------------------------------------------------
extern "C" void kernel_launch(void* const* d_in, const int* in_sizes, int n_in,
                              void* d_out, int out_size) {
    const float* node_inputs = (const float*)d_in[0];
    const float* edge_inputs = (const float*)d_in[1];
    const int*   src         = (const int*)  d_in[2];
    const int*   dst         = (const int*)  d_in[3];
    const float* W           = (const float*)d_in[4];
    const float* b           = (const float*)d_in[5];
    const float* eps         = (const float*)d_in[6];
    float*       out         = (float*)      d_out;

    k_zero_count<<<NBLK, SCAN_B>>>();
    k_hist<<<(N_EDGES + 255) / 256, 256>>>(dst);
    k_scan1<<<NBLK, SCAN_B>>>();
    k_scan2<<<1, 1>>>();
    k_scan3<<<NBLK, SCAN_B>>>();
    k_fill_perm<<<(N_EDGES + 255) / 256, 256>>>(dst);

    // warp per node: 100000 warps = 12500 blocks x 256 threads
    k_agg_linear<<<(N_NODES * 32 + 255) / 256, 256>>>(
        node_inputs, edge_inputs, src, W, b, eps, out);
}

// round 5
// speedup vs baseline: 1.3742x; 1.3742x over previous
#include <cuda_runtime.h>
#include <cuda_bf16.h>
#include <cstdint>

#define N_NODES 100000
#define N_EDGES 1600000
#define DFEAT   32

// Scratch aggregation buffer (12.8 MB) — __device__ global, no allocation.
__device__ float g_agg[(size_t)N_NODES * DFEAT];

// ---------------------------------------------------------------------------
// Edge phase: one thread per HALF-ROW PAIR. idx -> edge e = idx>>2,
// chunk c = idx&3; thread handles float4 chunks c and c+4 of edge e.
// One src/dst load pair serves both chunks; 2 independent REDs (ILP).
//   msg = relu(x[src] + e); red.global.add.v4.f32 into g_agg[dst].
// ---------------------------------------------------------------------------
__global__ void __launch_bounds__(256)
gine_edge_kernel(const float* __restrict__ node_inputs,
                 const float* __restrict__ edge_inputs,
                 const int*   __restrict__ src,
                 const int*   __restrict__ dst) {
    long long idx = (long long)blockIdx.x * blockDim.x + threadIdx.x;
    const long long total = (long long)N_EDGES * 4;  // 6.4M
    if (idx >= total) return;

    int e = (int)(idx >> 2);   // edge id
    int c = (int)(idx & 3);    // chunk pair: c and c+4

    int s = __ldg(&src[e]);
    int d = __ldg(&dst[e]);

    const float4* ep = reinterpret_cast<const float4*>(edge_inputs);
    const float4* np = reinterpret_cast<const float4*>(node_inputs);

    float4 ev0 = ep[(size_t)e * 8 + c];
    float4 ev1 = ep[(size_t)e * 8 + c + 4];
    float4 xv0 = np[(size_t)s * 8 + c];
    float4 xv1 = np[(size_t)s * 8 + c + 4];

    float4 m0, m1;
    m0.x = fmaxf(xv0.x + ev0.x, 0.f);
    m0.y = fmaxf(xv0.y + ev0.y, 0.f);
    m0.z = fmaxf(xv0.z + ev0.z, 0.f);
    m0.w = fmaxf(xv0.w + ev0.w, 0.f);
    m1.x = fmaxf(xv1.x + ev1.x, 0.f);
    m1.y = fmaxf(xv1.y + ev1.y, 0.f);
    m1.z = fmaxf(xv1.z + ev1.z, 0.f);
    m1.w = fmaxf(xv1.w + ev1.w, 0.f);

    float* ap0 = g_agg + (size_t)d * DFEAT + c * 4;
    float* ap1 = ap0 + 16;

    // Skip all-zero chunks (~6% of chunks after relu): fewer atomic lanes.
    if ((m0.x + m0.y + m0.z + m0.w) > 0.f) {
        asm volatile("red.global.add.v4.f32 [%0], {%1, %2, %3, %4};"
                     :: "l"(ap0), "f"(m0.x), "f"(m0.y), "f"(m0.z), "f"(m0.w)
                     : "memory");
    }
    if ((m1.x + m1.y + m1.z + m1.w) > 0.f) {
        asm volatile("red.global.add.v4.f32 [%0], {%1, %2, %3, %4};"
                     :: "l"(ap1), "f"(m1.x), "f"(m1.y), "f"(m1.z), "f"(m1.w)
                     : "memory");
    }
}

// ---------------------------------------------------------------------------
// Node phase. Warp per node; lane o = output feature.
//   h[k] held by lane k, broadcast via shfl; W row per lane in registers.
//   out[n][o] = b[o] + sum_k ((1+eps)*x[n][k] + agg[n][k]) * W[o][k]
// ---------------------------------------------------------------------------
__global__ void __launch_bounds__(256)
gine_node_kernel(const float* __restrict__ node_inputs,
                 const float* __restrict__ W,
                 const float* __restrict__ b,
                 const float* __restrict__ eps,
                 float*       __restrict__ out) {
    int gtid = blockIdx.x * blockDim.x + threadIdx.x;
    int n    = gtid >> 5;
    int lane = threadIdx.x & 31;
    if (n >= N_NODES) return;

    float w[32];
#pragma unroll
    for (int k = 0; k < 32; k++) w[k] = __ldg(&W[lane * 32 + k]);
    float bias = __ldg(&b[lane]);
    float ep1  = 1.0f + __ldg(&eps[0]);

    float h = ep1 * node_inputs[(size_t)n * 32 + lane]
            + g_agg[(size_t)n * 32 + lane];

    float a0 = bias, a1 = 0.f, a2 = 0.f, a3 = 0.f;
#pragma unroll
    for (int k = 0; k < 32; k += 4) {
        a0 = fmaf(__shfl_sync(0xffffffffu, h, k + 0), w[k + 0], a0);
        a1 = fmaf(__shfl_sync(0xffffffffu, h, k + 1), w[k + 1], a1);
        a2 = fmaf(__shfl_sync(0xffffffffu, h, k + 2), w[k + 2], a2);
        a3 = fmaf(__shfl_sync(0xffffffffu, h, k + 3), w[k + 3], a3);
    }
    out[(size_t)n * 32 + lane] = (a0 + a1) + (a2 + a3);
}

// ---------------------------------------------------------------------------
// Launch: memset(agg) -> edges -> nodes on the capture stream.
// Inputs: node_inputs, edge_inputs, src, dst, W, b, eps.
// ---------------------------------------------------------------------------
extern "C" void kernel_launch(void* const* d_in, const int* in_sizes, int n_in,
                              void* d_out, int out_size) {
    const float* node_inputs = (const float*)d_in[0];
    const float* edge_inputs = (const float*)d_in[1];
    const int*   src         = (const int*)  d_in[2];
    const int*   dst         = (const int*)  d_in[3];
    const float* W           = (const float*)d_in[4];
    const float* b           = (const float*)d_in[5];
    const float* eps         = (const float*)d_in[6];
    float*       out         = (float*)      d_out;

    // 1) zero agg via async memset (graph-capturable memset node)
    void* agg_ptr = nullptr;
    cudaGetSymbolAddress(&agg_ptr, g_agg);
    cudaMemsetAsync(agg_ptr, 0, (size_t)N_NODES * DFEAT * sizeof(float), 0);

    // 2) edge scatter: 6.4M threads (2 float4 chunks each)
    {
        long long total = (long long)N_EDGES * 4;
        int threads = 256;
        int blocks  = (int)((total + threads - 1) / threads);
        gine_edge_kernel<<<blocks, threads>>>(node_inputs, edge_inputs, src, dst);
    }
    // 3) node linear: exact warp per node
    {
        int threads = 256;                       // 8 warps/block
        int blocks  = (N_NODES * 32 + 255) / 256; // 12500
        gine_node_kernel<<<blocks, threads>>>(node_inputs, W, b, eps, out);
    }
}

// round 7
// speedup vs baseline: 3.9596x; 2.8814x over previous
#include <cuda_runtime.h>
#include <cuda_bf16.h>
#include <cstdint>

#define N_NODES 100000
#define N_EDGES 1600000
#define DFEAT   32

// Scratch aggregation buffer (12.8 MB) — __device__ global, no allocation.
__device__ float g_agg[(size_t)N_NODES * DFEAT];

// ---------------------------------------------------------------------------
// Edge phase: one thread per HALF-ROW PAIR. idx -> edge e = idx>>2,
// chunk c = idx&3; thread handles float4 chunks c and c+4 of edge e.
// One src/dst load pair serves both chunks; 2 independent REDs (ILP).
//   msg = relu(x[src] + e); red.global.add.v4.f32 into g_agg[dst].
// (Measured ~55us in R5 — near the LTS floor. Unchanged.)
// ---------------------------------------------------------------------------
__global__ void __launch_bounds__(256)
gine_edge_kernel(const float* __restrict__ node_inputs,
                 const float* __restrict__ edge_inputs,
                 const int*   __restrict__ src,
                 const int*   __restrict__ dst) {
    long long idx = (long long)blockIdx.x * blockDim.x + threadIdx.x;
    const long long total = (long long)N_EDGES * 4;  // 6.4M
    if (idx >= total) return;

    int e = (int)(idx >> 2);   // edge id
    int c = (int)(idx & 3);    // chunk pair: c and c+4

    int s = __ldg(&src[e]);
    int d = __ldg(&dst[e]);

    const float4* ep = reinterpret_cast<const float4*>(edge_inputs);
    const float4* np = reinterpret_cast<const float4*>(node_inputs);

    float4 ev0 = ep[(size_t)e * 8 + c];
    float4 ev1 = ep[(size_t)e * 8 + c + 4];
    float4 xv0 = np[(size_t)s * 8 + c];
    float4 xv1 = np[(size_t)s * 8 + c + 4];

    float4 m0, m1;
    m0.x = fmaxf(xv0.x + ev0.x, 0.f);
    m0.y = fmaxf(xv0.y + ev0.y, 0.f);
    m0.z = fmaxf(xv0.z + ev0.z, 0.f);
    m0.w = fmaxf(xv0.w + ev0.w, 0.f);
    m1.x = fmaxf(xv1.x + ev1.x, 0.f);
    m1.y = fmaxf(xv1.y + ev1.y, 0.f);
    m1.z = fmaxf(xv1.z + ev1.z, 0.f);
    m1.w = fmaxf(xv1.w + ev1.w, 0.f);

    float* ap0 = g_agg + (size_t)d * DFEAT + c * 4;
    float* ap1 = ap0 + 16;

    // Skip all-zero chunks after relu: fewer atomic lanes.
    if ((m0.x + m0.y + m0.z + m0.w) > 0.f) {
        asm volatile("red.global.add.v4.f32 [%0], {%1, %2, %3, %4};"
                     :: "l"(ap0), "f"(m0.x), "f"(m0.y), "f"(m0.z), "f"(m0.w)
                     : "memory");
    }
    if ((m1.x + m1.y + m1.z + m1.w) > 0.f) {
        asm volatile("red.global.add.v4.f32 [%0], {%1, %2, %3, %4};"
                     :: "l"(ap1), "f"(m1.x), "f"(m1.y), "f"(m1.z), "f"(m1.w)
                     : "memory");
    }
}

// ---------------------------------------------------------------------------
// Node phase: GRID-STRIDE warp per node (R3 form). W is loaded into
// registers ONCE per warp and amortized over ~6 nodes — this is the fix
// for R5's 349us L1tex-bound regression (W reload per node).
//   out[n][o] = b[o] + sum_k ((1+eps)*x[n][k] + agg[n][k]) * W[o][k]
// ---------------------------------------------------------------------------
__global__ void __launch_bounds__(256)
gine_node_kernel(const float* __restrict__ node_inputs,
                 const float* __restrict__ W,
                 const float* __restrict__ b,
                 const float* __restrict__ eps,
                 float*       __restrict__ out) {
    int gtid   = blockIdx.x * blockDim.x + threadIdx.x;
    int warp   = gtid >> 5;
    int lane   = threadIdx.x & 31;
    int nwarps = (gridDim.x * blockDim.x) >> 5;

    // Each lane o caches W[o][0..31] in registers — once per warp.
    float w[32];
#pragma unroll
    for (int k = 0; k < 32; k++) w[k] = __ldg(&W[lane * 32 + k]);
    float bias = __ldg(&b[lane]);
    float ep1  = 1.0f + __ldg(&eps[0]);

    for (int n = warp; n < N_NODES; n += nwarps) {
        float h = ep1 * node_inputs[(size_t)n * 32 + lane]
                + g_agg[(size_t)n * 32 + lane];

        float a0 = bias, a1 = 0.f, a2 = 0.f, a3 = 0.f;
#pragma unroll
        for (int k = 0; k < 32; k += 4) {
            a0 = fmaf(__shfl_sync(0xffffffffu, h, k + 0), w[k + 0], a0);
            a1 = fmaf(__shfl_sync(0xffffffffu, h, k + 1), w[k + 1], a1);
            a2 = fmaf(__shfl_sync(0xffffffffu, h, k + 2), w[k + 2], a2);
            a3 = fmaf(__shfl_sync(0xffffffffu, h, k + 3), w[k + 3], a3);
        }
        out[(size_t)n * 32 + lane] = (a0 + a1) + (a2 + a3);
    }
}

// ---------------------------------------------------------------------------
// Launch: memset(agg) -> edges -> nodes on the capture stream.
// Inputs: node_inputs, edge_inputs, src, dst, W, b, eps.
// ---------------------------------------------------------------------------
extern "C" void kernel_launch(void* const* d_in, const int* in_sizes, int n_in,
                              void* d_out, int out_size) {
    const float* node_inputs = (const float*)d_in[0];
    const float* edge_inputs = (const float*)d_in[1];
    const int*   src         = (const int*)  d_in[2];
    const int*   dst         = (const int*)  d_in[3];
    const float* W           = (const float*)d_in[4];
    const float* b           = (const float*)d_in[5];
    const float* eps         = (const float*)d_in[6];
    float*       out         = (float*)      d_out;

    // 1) zero agg via async memset (graph-capturable memset node)
    void* agg_ptr = nullptr;
    cudaGetSymbolAddress(&agg_ptr, g_agg);
    cudaMemsetAsync(agg_ptr, 0, (size_t)N_NODES * DFEAT * sizeof(float), 0);

    // 2) edge scatter: 6.4M threads (2 float4 chunks each)
    {
        long long total = (long long)N_EDGES * 4;
        int threads = 256;
        int blocks  = (int)((total + threads - 1) / threads);
        gine_edge_kernel<<<blocks, threads>>>(node_inputs, edge_inputs, src, dst);
    }
    // 3) node linear: grid-stride, 16384 warps (~6 nodes per warp)
    {
        int threads = 256;   // 8 warps/block
        int blocks  = 2048;  // 16384 warps
        gine_node_kernel<<<blocks, threads>>>(node_inputs, W, b, eps, out);
    }
}

// round 8
// speedup vs baseline: 6.9603x; 1.7578x over previous
#include <cuda_runtime.h>
#include <cuda_bf16.h>
#include <cstdint>

#define N_NODES 100000
#define N_EDGES 1600000
#define DFEAT   32

// Scratch aggregation buffer (12.8 MB) — __device__ global, no allocation.
__device__ float g_agg[(size_t)N_NODES * DFEAT];

// ---------------------------------------------------------------------------
// Edge phase: one thread per HALF-ROW PAIR (measured ~54us, near LTS floor;
// UNCHANGED). idx -> edge e = idx>>2, chunk c = idx&3; handles chunks c, c+4.
// ---------------------------------------------------------------------------
__global__ void __launch_bounds__(256)
gine_edge_kernel(const float* __restrict__ node_inputs,
                 const float* __restrict__ edge_inputs,
                 const int*   __restrict__ src,
                 const int*   __restrict__ dst) {
    long long idx = (long long)blockIdx.x * blockDim.x + threadIdx.x;
    const long long total = (long long)N_EDGES * 4;  // 6.4M
    if (idx >= total) return;

    int e = (int)(idx >> 2);
    int c = (int)(idx & 3);

    int s = __ldg(&src[e]);
    int d = __ldg(&dst[e]);

    const float4* ep = reinterpret_cast<const float4*>(edge_inputs);
    const float4* np = reinterpret_cast<const float4*>(node_inputs);

    float4 ev0 = ep[(size_t)e * 8 + c];
    float4 ev1 = ep[(size_t)e * 8 + c + 4];
    float4 xv0 = np[(size_t)s * 8 + c];
    float4 xv1 = np[(size_t)s * 8 + c + 4];

    float4 m0, m1;
    m0.x = fmaxf(xv0.x + ev0.x, 0.f);
    m0.y = fmaxf(xv0.y + ev0.y, 0.f);
    m0.z = fmaxf(xv0.z + ev0.z, 0.f);
    m0.w = fmaxf(xv0.w + ev0.w, 0.f);
    m1.x = fmaxf(xv1.x + ev1.x, 0.f);
    m1.y = fmaxf(xv1.y + ev1.y, 0.f);
    m1.z = fmaxf(xv1.z + ev1.z, 0.f);
    m1.w = fmaxf(xv1.w + ev1.w, 0.f);

    float* ap0 = g_agg + (size_t)d * DFEAT + c * 4;
    float* ap1 = ap0 + 16;

    if ((m0.x + m0.y + m0.z + m0.w) > 0.f) {
        asm volatile("red.global.add.v4.f32 [%0], {%1, %2, %3, %4};"
                     :: "l"(ap0), "f"(m0.x), "f"(m0.y), "f"(m0.z), "f"(m0.w)
                     : "memory");
    }
    if ((m1.x + m1.y + m1.z + m1.w) > 0.f) {
        asm volatile("red.global.add.v4.f32 [%0], {%1, %2, %3, %4};"
                     :: "l"(ap1), "f"(m1.x), "f"(m1.y), "f"(m1.z), "f"(m1.w)
                     : "memory");
    }
}

// ---------------------------------------------------------------------------
// Node phase REWRITE: thread per node, NO shuffles.
// W^T and b staged in smem (LDS.128 broadcast, conflict-free). Each thread:
// 16 front-batched LDG.128 (x + agg), h computed on the fly, 32 register
// accumulators updated rank-1: acc[o] += h[k] * Wt[k][o].
// ---------------------------------------------------------------------------
__global__ void __launch_bounds__(256)
gine_node_kernel(const float* __restrict__ node_inputs,
                 const float* __restrict__ W,
                 const float* __restrict__ b,
                 const float* __restrict__ eps,
                 float*       __restrict__ out) {
    __shared__ float Wt[32][32];   // Wt[k][o] = W[o][k]; reads are broadcast
    __shared__ float sb[32];

    int tid = threadIdx.x;
#pragma unroll
    for (int i = tid; i < 1024; i += 256) {
        int o = i >> 5, k = i & 31;
        Wt[k][o] = W[i];           // W row-major [o][k]
    }
    if (tid < 32) sb[tid] = b[tid];
    __syncthreads();

    float ep1 = 1.0f + __ldg(&eps[0]);

    int n = blockIdx.x * blockDim.x + tid;
    if (n >= N_NODES) return;

    const float4* xp = reinterpret_cast<const float4*>(node_inputs) + (size_t)n * 8;
    const float4* ap = reinterpret_cast<const float4*>(g_agg)       + (size_t)n * 8;

    // Front-batch all 16 loads (MLP=16).
    float4 xv[8], av[8];
#pragma unroll
    for (int c = 0; c < 8; c++) xv[c] = xp[c];
#pragma unroll
    for (int c = 0; c < 8; c++) av[c] = ap[c];

    float acc[32];
#pragma unroll
    for (int o = 0; o < 32; o++) acc[o] = sb[o];

#pragma unroll
    for (int c = 0; c < 8; c++) {
        float h0 = fmaf(ep1, xv[c].x, av[c].x);
        float h1 = fmaf(ep1, xv[c].y, av[c].y);
        float h2 = fmaf(ep1, xv[c].z, av[c].z);
        float h3 = fmaf(ep1, xv[c].w, av[c].w);
        float hh[4] = {h0, h1, h2, h3};
#pragma unroll
        for (int j = 0; j < 4; j++) {
            const float4* wrow = reinterpret_cast<const float4*>(Wt[c * 4 + j]);
            float hk = hh[j];
#pragma unroll
            for (int o4 = 0; o4 < 8; o4++) {
                float4 wv = wrow[o4];   // LDS.128 broadcast
                acc[o4 * 4 + 0] = fmaf(hk, wv.x, acc[o4 * 4 + 0]);
                acc[o4 * 4 + 1] = fmaf(hk, wv.y, acc[o4 * 4 + 1]);
                acc[o4 * 4 + 2] = fmaf(hk, wv.z, acc[o4 * 4 + 2]);
                acc[o4 * 4 + 3] = fmaf(hk, wv.w, acc[o4 * 4 + 3]);
            }
        }
    }

    float4* op = reinterpret_cast<float4*>(out) + (size_t)n * 8;
#pragma unroll
    for (int c = 0; c < 8; c++) {
        op[c] = make_float4(acc[c * 4 + 0], acc[c * 4 + 1],
                            acc[c * 4 + 2], acc[c * 4 + 3]);
    }
}

// ---------------------------------------------------------------------------
// Launch: memset(agg) -> edges -> nodes.
// Inputs: node_inputs, edge_inputs, src, dst, W, b, eps.
// ---------------------------------------------------------------------------
extern "C" void kernel_launch(void* const* d_in, const int* in_sizes, int n_in,
                              void* d_out, int out_size) {
    const float* node_inputs = (const float*)d_in[0];
    const float* edge_inputs = (const float*)d_in[1];
    const int*   src         = (const int*)  d_in[2];
    const int*   dst         = (const int*)  d_in[3];
    const float* W           = (const float*)d_in[4];
    const float* b           = (const float*)d_in[5];
    const float* eps         = (const float*)d_in[6];
    float*       out         = (float*)      d_out;

    void* agg_ptr = nullptr;
    cudaGetSymbolAddress(&agg_ptr, g_agg);
    cudaMemsetAsync(agg_ptr, 0, (size_t)N_NODES * DFEAT * sizeof(float), 0);

    {
        long long total = (long long)N_EDGES * 4;
        int threads = 256;
        int blocks  = (int)((total + threads - 1) / threads);
        gine_edge_kernel<<<blocks, threads>>>(node_inputs, edge_inputs, src, dst);
    }
    {
        int threads = 256;
        int blocks  = (N_NODES + threads - 1) / threads;  // 391
        gine_node_kernel<<<blocks, threads>>>(node_inputs, W, b, eps, out);
    }
}

// round 11
// speedup vs baseline: 7.3298x; 1.0531x over previous
#include <cuda_runtime.h>
#include <cuda_bf16.h>
#include <cstdint>

#define N_NODES 100000
#define N_EDGES 1600000
#define DFEAT   32

// Scratch aggregation buffer (12.8 MB) — __device__ global, no allocation.
__device__ float g_agg[(size_t)N_NODES * DFEAT];

// ---------------------------------------------------------------------------
// Edge phase: one thread per HALF-ROW PAIR (measured ~55us across R5/R7/R8,
// at the chip LTS cap — UNCHANGED).
// ---------------------------------------------------------------------------
__global__ void __launch_bounds__(256)
gine_edge_kernel(const float* __restrict__ node_inputs,
                 const float* __restrict__ edge_inputs,
                 const int*   __restrict__ src,
                 const int*   __restrict__ dst) {
    long long idx = (long long)blockIdx.x * blockDim.x + threadIdx.x;
    const long long total = (long long)N_EDGES * 4;  // 6.4M
    if (idx >= total) return;

    int e = (int)(idx >> 2);
    int c = (int)(idx & 3);

    int s = __ldg(&src[e]);
    int d = __ldg(&dst[e]);

    const float4* ep = reinterpret_cast<const float4*>(edge_inputs);
    const float4* np = reinterpret_cast<const float4*>(node_inputs);

    float4 ev0 = ep[(size_t)e * 8 + c];
    float4 ev1 = ep[(size_t)e * 8 + c + 4];
    float4 xv0 = np[(size_t)s * 8 + c];
    float4 xv1 = np[(size_t)s * 8 + c + 4];

    float4 m0, m1;
    m0.x = fmaxf(xv0.x + ev0.x, 0.f);
    m0.y = fmaxf(xv0.y + ev0.y, 0.f);
    m0.z = fmaxf(xv0.z + ev0.z, 0.f);
    m0.w = fmaxf(xv0.w + ev0.w, 0.f);
    m1.x = fmaxf(xv1.x + ev1.x, 0.f);
    m1.y = fmaxf(xv1.y + ev1.y, 0.f);
    m1.z = fmaxf(xv1.z + ev1.z, 0.f);
    m1.w = fmaxf(xv1.w + ev1.w, 0.f);

    float* ap0 = g_agg + (size_t)d * DFEAT + c * 4;
    float* ap1 = ap0 + 16;

    if ((m0.x + m0.y + m0.z + m0.w) > 0.f) {
        asm volatile("red.global.add.v4.f32 [%0], {%1, %2, %3, %4};"
                     :: "l"(ap0), "f"(m0.x), "f"(m0.y), "f"(m0.z), "f"(m0.w)
                     : "memory");
    }
    if ((m1.x + m1.y + m1.z + m1.w) > 0.f) {
        asm volatile("red.global.add.v4.f32 [%0], {%1, %2, %3, %4};"
                     :: "l"(ap1), "f"(m1.x), "f"(m1.y), "f"(m1.z), "f"(m1.w)
                     : "memory");
    }
}

// ---------------------------------------------------------------------------
// Node phase v3: thread per node, SMEM-staged rows.
// Global x/agg/out accessed fully coalesced (block-linear float4); per-thread
// row access via conflict-free padded LDS (stride 33 -> bank=(t+k)%32).
// Rank-1 GEMV with Wt broadcast LDS.128, 32 register accumulators.
// ---------------------------------------------------------------------------
__global__ void __launch_bounds__(256)
gine_node_kernel(const float* __restrict__ node_inputs,
                 const float* __restrict__ W,
                 const float* __restrict__ b,
                 const float* __restrict__ eps,
                 float*       __restrict__ out) {
    __shared__ float Wt[32][32];        // Wt[k][o] = W[o][k]
    __shared__ float sb[32];
    __shared__ float stage[256 * 33];   // padded row staging (33.8 KB)

    int tid = threadIdx.x;
#pragma unroll
    for (int i = tid; i < 1024; i += 256) {
        int o = i >> 5, k = i & 31;
        Wt[k][o] = W[i];
    }
    if (tid < 32) sb[tid] = b[tid];

    int base = blockIdx.x * 256;
    int rows = N_NODES - base; if (rows > 256) rows = 256;
    float ep1 = 1.0f + __ldg(&eps[0]);

    const float4* xp = reinterpret_cast<const float4*>(node_inputs);
    const float4* ap = reinterpret_cast<const float4*>(g_agg);

    // Stage x (coalesced float4 loads -> padded smem).
#pragma unroll
    for (int i4 = tid; i4 < 2048; i4 += 256) {
        int row = i4 >> 3, c = i4 & 7;
        float4 v = (row < rows) ? xp[(size_t)(base + row) * 8 + c]
                                : make_float4(0.f, 0.f, 0.f, 0.f);
        float* s = &stage[row * 33 + c * 4];
        s[0] = v.x; s[1] = v.y; s[2] = v.z; s[3] = v.w;
    }
    __syncthreads();

    float h[32];
#pragma unroll
    for (int k = 0; k < 32; k++) h[k] = stage[tid * 33 + k];
    __syncthreads();

    // Stage agg.
#pragma unroll
    for (int i4 = tid; i4 < 2048; i4 += 256) {
        int row = i4 >> 3, c = i4 & 7;
        float4 v = (row < rows) ? ap[(size_t)(base + row) * 8 + c]
                                : make_float4(0.f, 0.f, 0.f, 0.f);
        float* s = &stage[row * 33 + c * 4];
        s[0] = v.x; s[1] = v.y; s[2] = v.z; s[3] = v.w;
    }
    __syncthreads();

#pragma unroll
    for (int k = 0; k < 32; k++) h[k] = fmaf(ep1, h[k], stage[tid * 33 + k]);

    // Rank-1 GEMV: acc[o] += h[k] * Wt[k][o] (Wt via broadcast LDS.128).
    float acc[32];
#pragma unroll
    for (int o = 0; o < 32; o++) acc[o] = sb[o];
#pragma unroll
    for (int k = 0; k < 32; k++) {
        float hk = h[k];
        const float4* wrow = reinterpret_cast<const float4*>(Wt[k]);
#pragma unroll
        for (int o4 = 0; o4 < 8; o4++) {
            float4 wv = wrow[o4];
            acc[o4 * 4 + 0] = fmaf(hk, wv.x, acc[o4 * 4 + 0]);
            acc[o4 * 4 + 1] = fmaf(hk, wv.y, acc[o4 * 4 + 1]);
            acc[o4 * 4 + 2] = fmaf(hk, wv.z, acc[o4 * 4 + 2]);
            acc[o4 * 4 + 3] = fmaf(hk, wv.w, acc[o4 * 4 + 3]);
        }
    }

    // Stage result and write back coalesced.
    __syncthreads();
#pragma unroll
    for (int k = 0; k < 32; k++) stage[tid * 33 + k] = acc[k];
    __syncthreads();

    float4* op = reinterpret_cast<float4*>(out);
#pragma unroll
    for (int i4 = tid; i4 < 2048; i4 += 256) {
        int row = i4 >> 3, c = i4 & 7;
        if (row < rows) {
            float* s = &stage[row * 33 + c * 4];
            op[(size_t)(base + row) * 8 + c] = make_float4(s[0], s[1], s[2], s[3]);
        }
    }
}

// ---------------------------------------------------------------------------
// Launch: memset(agg) -> edges -> nodes.
// Inputs: node_inputs, edge_inputs, src, dst, W, b, eps.
// ---------------------------------------------------------------------------
extern "C" void kernel_launch(void* const* d_in, const int* in_sizes, int n_in,
                              void* d_out, int out_size) {
    const float* node_inputs = (const float*)d_in[0];
    const float* edge_inputs = (const float*)d_in[1];
    const int*   src         = (const int*)  d_in[2];
    const int*   dst         = (const int*)  d_in[3];
    const float* W           = (const float*)d_in[4];
    const float* b           = (const float*)d_in[5];
    const float* eps         = (const float*)d_in[6];
    float*       out         = (float*)      d_out;

    void* agg_ptr = nullptr;
    cudaGetSymbolAddress(&agg_ptr, g_agg);
    cudaMemsetAsync(agg_ptr, 0, (size_t)N_NODES * DFEAT * sizeof(float), 0);

    {
        long long total = (long long)N_EDGES * 4;
        int threads = 256;
        int blocks  = (int)((total + threads - 1) / threads);
        gine_edge_kernel<<<blocks, threads>>>(node_inputs, edge_inputs, src, dst);
    }
    {
        int threads = 256;
        int blocks  = (N_NODES + threads - 1) / threads;  // 391
        gine_node_kernel<<<blocks, threads>>>(node_inputs, W, b, eps, out);
    }
}